// round 13
// baseline (speedup 1.0000x reference)
#include <cuda_runtime.h>
#include <math.h>

typedef unsigned long long u64;

// Problem constants (fixed by the reference)
constexpr int Hc = 512, Wc = 512;
constexpr int Bc = 2, Gc = 4, Fc = 9, Cc = 3;
constexpr int Nn = Hc * Wc;

constexpr int TILE = 32;
constexpr int NTHREADS = 512;

// ---- Kernel 1 geometry: fM region = rows y0..y0+32 (33), cols x0-1..x0+32 (34)
constexpr int NR1 = 33, NC1 = 34;
constexpr int NF  = NR1 * NC1;     // 1122
constexpr int NFp = NF + 2;        // aligned pad
// K1 smem: float4 A plane, float4 B plane, f32 E plane
constexpr int K1_A = 0;
constexpr int K1_B = K1_A + 4 * NFp;
constexpr int K1_E = K1_B + 4 * NFp;
constexpr int K1_FLOATS = K1_E + NFp;          // 10098+... = 9*NFp
constexpr int K1_SMEM = K1_FLOATS * 4;         // ~40.5 KB -> 3 blocks/SM (reg-capped)

// ---- Kernel 2 geometry: ew window rows y0-2..y0+32 (35), cols x0-2..x0+33 (36)
constexpr int RF  = 36;            // window cols / region stride
constexpr int RD  = TILE + 2;      // 34
constexpr int NP2 = 35 * RF;       // 1260 per plane
constexpr int ND  = RD * RD;       // 1156
constexpr int K2_EW = 0;           // 5 planes, stride NP2
constexpr int K2_SD = 5 * NP2;     // byte 25200 (16B aligned) : float4 plane, ND entries
constexpr int K2_FLOATS = K2_SD + 4 * ND;      // 10924
constexpr int K2_SMEM = K2_FLOATS * 4;         // 43696 B

// Global scratch: ew field, layout (bg, dir, N)
__device__ float g_ew[Bc * Gc * 5 * Nn];       // 41.9 MB

// Pair-packed multiM: per (g,f): pairs (c0,c1)(c2,c3)(c4,c5)(c6,c7)(c8,0)
__constant__ u64 cMp[Gc * Fc * 5];
__device__   u64 g_packM[Gc * Fc * 5];

__device__ __forceinline__ u64 pk2(float lo, float hi) {
    u64 r; asm("mov.b64 %0, {%1, %2};" : "=l"(r) : "f"(lo), "f"(hi)); return r;
}
__device__ __forceinline__ void upk2(float& lo, float& hi, u64 v) {
    asm("mov.b64 {%0, %1}, %2;" : "=f"(lo), "=f"(hi) : "l"(v));
}
__device__ __forceinline__ u64 ffma2(u64 a, u64 b, u64 c) {
    u64 d; asm("fma.rn.f32x2 %0, %1, %2, %3;" : "=l"(d) : "l"(a), "l"(b), "l"(c)); return d;
}
__device__ __forceinline__ u64 fmul2(u64 a, u64 b) {
    u64 d; asm("mul.rn.f32x2 %0, %1, %2;" : "=l"(d) : "l"(a), "l"(b)); return d;
}

__global__ void repack_kernel(const float* __restrict__ M) {
    int i = threadIdx.x;
    if (i < Gc * Fc * 5) {
        int g = i / 45, r = i % 45, f = r / 5, v = r % 5;
        float lo = M[g * 81 + f * 9 + 2 * v];
        float hi = (2 * v + 1 < 9) ? M[g * 81 + f * 9 + 2 * v + 1] : 0.f;
        g_packM[i] = pk2(lo, hi);
    }
}

__device__ __forceinline__ float eclip(float s) {
    // NaN-safe: fmaxf(NaN,-10) = -10
    return __expf(fminf(fmaxf(s, -10.f), 10.f));
}

// Packed feature transform: writes float4-planes at idx.
__device__ __forceinline__ void compute_fm(const float* __restrict__ imgbg, int p,
                                           const u64* __restrict__ mp,
                                           ulonglong2* __restrict__ A2,
                                           ulonglong2* __restrict__ B2,
                                           float* __restrict__ sE, int idx) {
    u64 a0 = 0ull, a1 = 0ull, a2 = 0ull, a3 = 0ull, a4 = 0ull;
    float ss = 0.f;
    #pragma unroll
    for (int f = 0; f < 9; f++) {
        const float x = __ldg(imgbg + (size_t)f * Nn + p);
        ss = fmaf(x, x, ss);
        const u64 xx = pk2(x, x);
        a0 = ffma2(xx, mp[f * 5 + 0], a0);
        a1 = ffma2(xx, mp[f * 5 + 1], a1);
        a2 = ffma2(xx, mp[f * 5 + 2], a2);
        a3 = ffma2(xx, mp[f * 5 + 3], a3);
        a4 = ffma2(xx, mp[f * 5 + 4], a4);
    }
    const float inv = rsqrtf(fmaxf(ss, 1e-24f));
    const u64 ii = pk2(inv, inv);
    const u64 r0 = fmul2(a0, ii), r1 = fmul2(a1, ii), r2 = fmul2(a2, ii),
              r3 = fmul2(a3, ii), r4 = fmul2(a4, ii);   // r4 hi lane = 0
    A2[idx] = make_ulonglong2(r0, r1);   // STS.128
    B2[idx] = make_ulonglong2(r2, r3);   // STS.128
    float v8, h; upk2(v8, h, r4); (void)h;
    sE[idx] = v8;
}

__device__ __forceinline__ void zero_fm(ulonglong2* A2, ulonglong2* B2, float* sE, int idx) {
    A2[idx] = make_ulonglong2(0ull, 0ull);
    B2[idx] = make_ulonglong2(0ull, 0ull);
    sE[idx] = 0.f;
}

// dot of register vector with fM vector at slot j (2x LDS.128 + LDS.32)
__device__ __forceinline__ float dotq(const ulonglong2 aA, const ulonglong2 aB, float a8,
                                      const ulonglong2* __restrict__ A2,
                                      const ulonglong2* __restrict__ B2,
                                      const float* __restrict__ sE, int j) {
    const ulonglong2 qA = A2[j];
    const ulonglong2 qB = B2[j];
    u64 acc = fmul2(aA.x, qA.x);
    acc = ffma2(aA.y, qA.y, acc);
    acc = ffma2(aB.x, qB.x, acc);
    acc = ffma2(aB.y, qB.y, acc);
    float lo, hi; upk2(lo, hi, acc);
    return fmaf(a8, sE[j], lo + hi);
}

// =============================== Kernel 1 ===============================
// fM over 33x34 region (1px halo), then 5 ew dirs per owned pixel -> g_ew.
__global__ void __launch_bounds__(NTHREADS, 3)
glr_k1(const float* __restrict__ img)
{
    extern __shared__ float sm[];
    ulonglong2* __restrict__ A2 = reinterpret_cast<ulonglong2*>(sm + K1_A);
    ulonglong2* __restrict__ B2 = reinterpret_cast<ulonglong2*>(sm + K1_B);
    float*      __restrict__ sE = sm + K1_E;

    const int tid = threadIdx.x;
    const int bg  = blockIdx.z;
    const int g   = bg & (Gc - 1);
    const int x0  = blockIdx.x * TILE;
    const int y0  = blockIdx.y * TILE;
    // interior: region rows y0..y0+32 and cols x0-1..x0+32 all in-image
    const bool interior = (blockIdx.x >= 1) && (blockIdx.x <= 14) && (blockIdx.y <= 14);

    const float* __restrict__ imgbg = img + (size_t)bg * Fc * Nn;
    const u64* __restrict__ mp = cMp + g * 45;

    // ---- fill fM region ----
    if (interior) {
        const int pbase = y0 * Wc + (x0 - 1);
        for (int idx = tid; idx < NF; idx += NTHREADS) {
            const int ry = idx / NC1;
            const int rx = idx - ry * NC1;
            compute_fm(imgbg, pbase + ry * Wc + rx, mp, A2, B2, sE, idx);
        }
    } else {
        for (int idx = tid; idx < NF; idx += NTHREADS) {
            const int ry = idx / NC1;
            const int rx = idx - ry * NC1;
            const int gy = y0 + ry;
            const int gx = x0 - 1 + rx;
            if ((unsigned)gy < (unsigned)Hc && (unsigned)gx < (unsigned)Wc)
                compute_fm(imgbg, gy * Wc + gx, mp, A2, B2, sE, idx);
            else
                zero_fm(A2, B2, sE, idx);
        }
    }
    __syncthreads();

    // ---- 5 dots per owned pixel (exactly 2 px/thread) -> global ew planes ----
    float* __restrict__ ewbg = g_ew + (size_t)bg * 5 * Nn;
    #pragma unroll
    for (int k = 0; k < 2; k++) {
        const int q = tid + k * NTHREADS;      // 0..1023
        const int ty = q >> 5;
        const int tx = q & 31;
        const int c = ty * NC1 + tx + 1;

        const ulonglong2 aA = A2[c];
        const ulonglong2 aB = B2[c];
        const float a8 = sE[c];

        // self from registers
        u64 sd = fmul2(aA.x, aA.x);
        sd = ffma2(aA.y, aA.y, sd);
        sd = ffma2(aB.x, aB.x, sd);
        sd = ffma2(aB.y, aB.y, sd);
        float lo, hi; upk2(lo, hi, sd);
        const float eself = eclip(fmaf(a8, a8, lo + hi));

        float e1, e2, e3, e4;
        if (interior) {
            e1 = eclip(dotq(aA, aB, a8, A2, B2, sE, c + 1));          // E
            e2 = eclip(dotq(aA, aB, a8, A2, B2, sE, c + NC1 - 1));    // SW
            e3 = eclip(dotq(aA, aB, a8, A2, B2, sE, c + NC1));        // S
            e4 = eclip(dotq(aA, aB, a8, A2, B2, sE, c + NC1 + 1));    // SE
        } else {
            const int gy = y0 + ty;
            const int gx = x0 + tx;
            const bool sOK = (gy + 1 < Hc);
            e1 = (gx + 1 < Wc)          ? eclip(dotq(aA, aB, a8, A2, B2, sE, c + 1))       : 0.f;
            e2 = (sOK && gx - 1 >= 0)   ? eclip(dotq(aA, aB, a8, A2, B2, sE, c + NC1 - 1)) : 0.f;
            e3 = sOK                    ? eclip(dotq(aA, aB, a8, A2, B2, sE, c + NC1))     : 0.f;
            e4 = (sOK && gx + 1 < Wc)   ? eclip(dotq(aA, aB, a8, A2, B2, sE, c + NC1 + 1)) : 0.f;
        }

        const int p = (y0 + ty) * Wc + (x0 + tx);
        ewbg[p]          = eself;
        ewbg[Nn + p]     = e1;
        ewbg[2 * Nn + p] = e2;
        ewbg[3 * Nn + p] = e3;
        ewbg[4 * Nn + p] = e4;
    }
}

// =============================== Kernel 2 ===============================
// Stage ew window (35x36 x 5 dirs) from g_ew, then deg/dinv + aggregation + out.
__global__ void __launch_bounds__(NTHREADS, 3)
glr_k2(const float* __restrict__ sig,
       float* __restrict__ out)
{
    extern __shared__ float sm[];
    float*  __restrict__ sEw = sm + K2_EW;                       // 5 planes, stride NP2
    float4* __restrict__ sSD = reinterpret_cast<float4*>(sm + K2_SD);

    const int tid = threadIdx.x;
    const int bg  = blockIdx.z;
    const int x0  = blockIdx.x * TILE;
    const int y0  = blockIdx.y * TILE;
    const bool interior = (blockIdx.x >= 1) && (blockIdx.x <= 14) &&
                          (blockIdx.y >= 1) && (blockIdx.y <= 14);

    const float* __restrict__ sigbg = sig + (size_t)bg * Cc * Nn;
    const float* __restrict__ ewbg  = g_ew + (size_t)bg * 5 * Nn;

    // ---- stage ew window: rows y0-2..y0+32, cols x0-2..x0+33 ----
    if (interior) {
        const int pbase = (y0 - 2) * Wc + (x0 - 2);
        for (int i = tid; i < 5 * NP2; i += NTHREADS) {
            const int t = i / NP2;
            const int rem = i - t * NP2;
            const int row = rem / RF;
            const int col = rem - row * RF;
            sm[K2_EW + i] = __ldg(ewbg + (size_t)t * Nn + pbase + row * Wc + col);
        }
    } else {
        for (int i = tid; i < 5 * NP2; i += NTHREADS) {
            const int t = i / NP2;
            const int rem = i - t * NP2;
            const int row = rem / RF;
            const int col = rem - row * RF;
            const int gy = y0 - 2 + row;
            const int gx = x0 - 2 + col;
            const bool inb = ((unsigned)gy < (unsigned)Hc) && ((unsigned)gx < (unsigned)Wc);
            sm[K2_EW + i] = inb ? __ldg(ewbg + (size_t)t * Nn + gy * Wc + gx) : 0.f;
        }
    }
    __syncthreads();

    // ---- deg -> dinv + prescaled float4 record over 34x34 ----
    if (interior) {
        const int pbase = (y0 - 1) * Wc + (x0 - 1);
        for (int idx = tid; idx < ND; idx += NTHREADS) {
            const int ly = idx / RD;
            const int lx = idx - ly * RD;
            const int r = (ly + 1) * RF + (lx + 1);
            float deg = sEw[r] + sEw[NP2 + r] + sEw[2 * NP2 + r]
                      + sEw[3 * NP2 + r] + sEw[4 * NP2 + r];
            deg += sEw[4 * NP2 + r - RF - 1];  // NW = SE of up-left
            deg += sEw[3 * NP2 + r - RF];      // N  = S  of up
            deg += sEw[2 * NP2 + r - RF + 1];  // NE = SW of up-right
            deg += sEw[NP2 + r - 1];           // W  = E  of left
            const float dinv = rsqrtf(deg);    // deg >= 1
            const int p = pbase + ly * Wc + lx;
            float4 sd;
            sd.x = __ldg(sigbg + p) * dinv;
            sd.y = __ldg(sigbg + Nn + p) * dinv;
            sd.z = __ldg(sigbg + 2 * Nn + p) * dinv;
            sd.w = dinv;
            sSD[idx] = sd;
        }
    } else {
        for (int idx = tid; idx < ND; idx += NTHREADS) {
            const int ly = idx / RD;
            const int lx = idx - ly * RD;
            const int gy = y0 - 1 + ly;
            const int gx = x0 - 1 + lx;
            const bool inb = ((unsigned)gy < (unsigned)Hc) && ((unsigned)gx < (unsigned)Wc);
            const int r = (ly + 1) * RF + (lx + 1);
            float dinv = 0.f;
            if (inb) {
                float deg = sEw[r] + sEw[NP2 + r] + sEw[2 * NP2 + r]
                          + sEw[3 * NP2 + r] + sEw[4 * NP2 + r];
                deg += sEw[4 * NP2 + r - RF - 1];
                deg += sEw[3 * NP2 + r - RF];
                deg += sEw[2 * NP2 + r - RF + 1];
                deg += sEw[NP2 + r - 1];
                dinv = rsqrtf(deg);
            }
            const int p = gy * Wc + gx;
            float4 sd;
            sd.x = inb ? __ldg(sigbg + p) * dinv          : 0.f;
            sd.y = inb ? __ldg(sigbg + Nn + p) * dinv     : 0.f;
            sd.z = inb ? __ldg(sigbg + 2 * Nn + p) * dinv : 0.f;
            sd.w = dinv;
            sSD[idx] = sd;
        }
    }
    __syncthreads();

    // ---- aggregation + output ----
    float* __restrict__ outbg = out + (size_t)bg * Cc * Nn;
    #pragma unroll
    for (int k = 0; k < 2; k++) {
        const int idx = tid + k * NTHREADS;       // 0..1023
        const int ly = idx >> 5;
        const int lx = idx & 31;
        const int r = (ly + 2) * RF + (lx + 2);
        const int d = (ly + 1) * RD + (lx + 1);

        const float4 c = sSD[d];
        const float dp = c.w;
        u64 S01 = 0ull;
        float S2 = 0.f;

        #define GLR_ACC(nn, ww) do {                         \
            const float _w = (ww);                           \
            const float4 _nb = sSD[(nn)];                    \
            S01 = ffma2(pk2(_nb.x, _nb.y), pk2(_w, _w), S01);\
            S2  = fmaf(_nb.z, _w, S2);                       \
        } while (0)

        GLR_ACC(d - RD - 1, sEw[4 * NP2 + r - RF - 1]);  // NW
        GLR_ACC(d - RD,     sEw[3 * NP2 + r - RF]);      // N
        GLR_ACC(d - RD + 1, sEw[2 * NP2 + r - RF + 1]);  // NE
        GLR_ACC(d - 1,      sEw[NP2 + r - 1]);           // W
        {
            const float w = sEw[r];                      // self
            S01 = ffma2(pk2(c.x, c.y), pk2(w, w), S01);
            S2  = fmaf(c.z, w, S2);
        }
        GLR_ACC(d + 1,      sEw[NP2 + r]);               // E
        GLR_ACC(d + RD - 1, sEw[2 * NP2 + r]);           // SW
        GLR_ACC(d + RD,     sEw[3 * NP2 + r]);           // S
        GLR_ACC(d + RD + 1, sEw[4 * NP2 + r]);           // SE
        #undef GLR_ACC

        float S0, S1; upk2(S0, S1, S01);
        const float inv = __fdividef(1.0f, dp);          // dp in (0,1]
        const int p = (y0 + ly) * Wc + (x0 + lx);
        outbg[p]          = fmaf(-dp, S0, c.x * inv);
        outbg[Nn + p]     = fmaf(-dp, S1, c.y * inv);
        outbg[2 * Nn + p] = fmaf(-dp, S2, c.z * inv);
    }
}

extern "C" void kernel_launch(void* const* d_in, const int* in_sizes, int n_in,
                              void* d_out, int out_size) {
    const float* img = (const float*)d_in[0];  // (B,G,F,H,W)
    const float* sig = (const float*)d_in[1];  // (B,G,C,H,W)
    const float* M   = (const float*)d_in[2];  // (G,F,F)
    float* out = (float*)d_out;

    cudaFuncSetAttribute(glr_k1, cudaFuncAttributeMaxDynamicSharedMemorySize, K1_SMEM);
    cudaFuncSetAttribute(glr_k2, cudaFuncAttributeMaxDynamicSharedMemorySize, K2_SMEM);

    repack_kernel<<<1, 192>>>(M);
    void* packed_ptr = nullptr;
    cudaGetSymbolAddress(&packed_ptr, g_packM);
    cudaMemcpyToSymbolAsync(cMp, packed_ptr, Gc * Fc * 5 * sizeof(u64),
                            0, cudaMemcpyDeviceToDevice, 0);

    dim3 grid(Wc / TILE, Hc / TILE, Bc * Gc);
    glr_k1<<<grid, NTHREADS, K1_SMEM>>>(img);
    glr_k2<<<grid, NTHREADS, K2_SMEM>>>(sig, out);
}

// round 14
// speedup vs baseline: 1.2973x; 1.2973x over previous
#include <cuda_runtime.h>
#include <math.h>

typedef unsigned long long u64;

// Problem constants (fixed by the reference)
constexpr int Hc = 512, Wc = 512;
constexpr int Bc = 2, Gc = 4, Fc = 9, Cc = 3;
constexpr int Nn = Hc * Wc;

// Tiling
constexpr int TILE = 32;           // output tile
constexpr int RF   = TILE + 4;     // 36: fM + ew region (2-pixel halo), offset -2
constexpr int RD   = TILE + 2;     // 34: dinv/sig region (1-pixel halo), offset -1
constexpr int NP   = RF * RF;      // 1296: fM plane size
constexpr int NP2  = (RF - 1) * RF;// 1260: ew plane size (row 35 never consumed)
constexpr int ND   = RD * RD;      // 1156

constexpr int NTHREADS = 512;

// SMEM layout (floats). fM pair-planes are dead after phase 2a; sig planes alias them.
constexpr int OFF_EW = 0;
constexpr int SZ_EW  = 5 * NP2;              // 6300 (self,E,SW,S,SE planes, stride NP2)
constexpr int OFF_U  = OFF_EW + SZ_EW;       // 6300 floats (byte 25200, 8B aligned)
constexpr int FA = OFF_U;                    // u64 plane: (v0,v1)  NP entries
constexpr int FB = OFF_U + 2 * NP;           // u64 plane: (v2,v3)
constexpr int FC = OFF_U + 4 * NP;           // u64 plane: (v4,v5)
constexpr int FD = OFF_U + 6 * NP;           // u64 plane: (v6,v7)
constexpr int FE = OFF_U + 8 * NP;           // f32 plane: v8, NP + 40 pad
constexpr int SM_FLOATS = OFF_U + 9 * NP + 40;   // 18004
constexpr int SMEM_BYTES = SM_FLOATS * 4;        // 72016 B -> 3 blocks/SM

// Padded multiM in constant memory: per (g,f) a 10-float row = 5 aligned u64 pairs
// (c0,c1)(c2,c3)(c4,c5)(c6,c7)(c8,pad). Filled by ONE cudaMemcpy2DAsync from M
// (36B rows -> 40B rows). Pad lanes are never written; __constant__ zero-init keeps
// them 0, and the kernel never consumes them anyway (see self-dot below).
__constant__ u64 cMp[Gc * Fc * 5];

__device__ __forceinline__ u64 pk2(float lo, float hi) {
    u64 r; asm("mov.b64 %0, {%1, %2};" : "=l"(r) : "f"(lo), "f"(hi)); return r;
}
__device__ __forceinline__ void upk2(float& lo, float& hi, u64 v) {
    asm("mov.b64 {%0, %1}, %2;" : "=f"(lo), "=f"(hi) : "l"(v));
}
__device__ __forceinline__ u64 ffma2(u64 a, u64 b, u64 c) {
    u64 d; asm("fma.rn.f32x2 %0, %1, %2, %3;" : "=l"(d) : "l"(a), "l"(b), "l"(c)); return d;
}
__device__ __forceinline__ u64 fmul2(u64 a, u64 b) {
    u64 d; asm("mul.rn.f32x2 %0, %1, %2;" : "=l"(d) : "l"(a), "l"(b)); return d;
}

__device__ __forceinline__ float eclip(float s) {
    // NaN-safe: fmaxf(NaN,-10) = -10
    return __expf(fminf(fmaxf(s, -10.f), 10.f));
}

// Packed feature transform: loads 9 img floats at p, normalizes, applies M.
// Writes pair-planes at index idx; returns self-similarity dot.
// Self-dot uses only r0..r3 pairs + v8^2, so the pad lane of the 5th M-pair can
// never leak into results even if non-zero.
__device__ __forceinline__ float compute_fm(const float* __restrict__ imgbg, int p,
                                            const u64* __restrict__ mp,
                                            u64* sA, u64* sB, u64* sC, u64* sD,
                                            float* sE, int idx) {
    u64 a0 = 0ull, a1 = 0ull, a2 = 0ull, a3 = 0ull, a4 = 0ull;
    float ss = 0.f;
    #pragma unroll
    for (int f = 0; f < 9; f++) {
        const float x = __ldg(imgbg + (size_t)f * Nn + p);
        ss = fmaf(x, x, ss);
        const u64 xx = pk2(x, x);
        a0 = ffma2(xx, mp[f * 5 + 0], a0);
        a1 = ffma2(xx, mp[f * 5 + 1], a1);
        a2 = ffma2(xx, mp[f * 5 + 2], a2);
        a3 = ffma2(xx, mp[f * 5 + 3], a3);
        a4 = ffma2(xx, mp[f * 5 + 4], a4);
    }
    const float inv = rsqrtf(fmaxf(ss, 1e-24f));
    const u64 ii = pk2(inv, inv);
    const u64 r0 = fmul2(a0, ii), r1 = fmul2(a1, ii), r2 = fmul2(a2, ii),
              r3 = fmul2(a3, ii), r4 = fmul2(a4, ii);
    sA[idx] = r0; sB[idx] = r1; sC[idx] = r2; sD[idx] = r3;
    float v8, h; upk2(v8, h, r4); (void)h;
    sE[idx] = v8;
    // self-dot from r0..r3 pairs + v8^2 (pad-lane-free)
    u64 sd = fmul2(r0, r0);
    sd = ffma2(r1, r1, sd); sd = ffma2(r2, r2, sd); sd = ffma2(r3, r3, sd);
    float lo, hi2; upk2(lo, hi2, sd);
    return fmaf(v8, v8, lo + hi2);
}

// Scalar vector fetch from pair planes (boundary path)
__device__ __forceinline__ void load_vec(const u64* sA, const u64* sB, const u64* sC,
                                         const u64* sD, const float* sE, int idx,
                                         float a[9]) {
    upk2(a[0], a[1], sA[idx]);
    upk2(a[2], a[3], sB[idx]);
    upk2(a[4], a[5], sC[idx]);
    upk2(a[6], a[7], sD[idx]);
    a[8] = sE[idx];
}

__device__ __forceinline__ float dot9s(const float a[9], const float b[9]) {
    float s = a[0] * b[0];
    #pragma unroll
    for (int f = 1; f < 9; f++) s = fmaf(a[f], b[f], s);
    return s;
}

__global__ void __launch_bounds__(NTHREADS, 3)
glr_fused_kernel(const float* __restrict__ img,
                 const float* __restrict__ sig,
                 float* __restrict__ out)
{
    extern __shared__ float sm[];
    float* __restrict__ sEw = sm + OFF_EW;           // 5 planes, stride NP2
    u64*   __restrict__ sA  = reinterpret_cast<u64*>(sm + FA);
    u64*   __restrict__ sB  = reinterpret_cast<u64*>(sm + FB);
    u64*   __restrict__ sC  = reinterpret_cast<u64*>(sm + FC);
    u64*   __restrict__ sD  = reinterpret_cast<u64*>(sm + FD);
    float* __restrict__ sE  = sm + FE;
    // sig planes alias the fM union (fM dead after phase 2a)
    u64*   __restrict__ sP01 = reinterpret_cast<u64*>(sm + OFF_U);  // (s0',s1') ND entries
    float* __restrict__ sP2  = sm + OFF_U + 2 * ND;
    float* __restrict__ sDv  = sm + OFF_U + 3 * ND;

    const int tid = threadIdx.x;
    const int bg  = blockIdx.z;
    const int g   = bg & (Gc - 1);
    const int x0  = blockIdx.x * TILE;
    const int y0  = blockIdx.y * TILE;
    const bool interior = (blockIdx.x >= 1) && (blockIdx.x <= 14) &&
                          (blockIdx.y >= 1) && (blockIdx.y <= 14);

    const float* __restrict__ imgbg = img + (size_t)bg * Fc * Nn;
    const float* __restrict__ sigbg = sig + (size_t)bg * Cc * Nn;
    const u64* __restrict__ mp = cMp + g * 45;

    // ------- Phase 1: fM pair-planes over 36x36 + self-similarity plane -------
    if (interior) {
        const int pbase = (y0 - 2) * Wc + (x0 - 2);
        for (int idx = tid; idx < NP; idx += NTHREADS) {
            const int ry = idx / RF;
            const int rx = idx - ry * RF;
            const float s = compute_fm(imgbg, pbase + ry * Wc + rx, mp,
                                       sA, sB, sC, sD, sE, idx);
            if (idx < NP2) sEw[idx] = eclip(s);   // row 35 self never consumed
        }
    } else {
        for (int idx = tid; idx < NP; idx += NTHREADS) {
            const int ry = idx / RF;
            const int rx = idx - ry * RF;
            const int gy = y0 - 2 + ry;
            const int gx = x0 - 2 + rx;
            if ((unsigned)gy < (unsigned)Hc && (unsigned)gx < (unsigned)Wc) {
                const float s = compute_fm(imgbg, gy * Wc + gx, mp,
                                           sA, sB, sC, sD, sE, idx);
                if (idx < NP2) sEw[idx] = eclip(s);
            } else {
                sA[idx] = 0ull; sB[idx] = 0ull; sC[idx] = 0ull; sD[idx] = 0ull;
                sE[idx] = 0.f;
                if (idx < NP2) sEw[idx] = 0.f;
            }
        }
    }
    __syncthreads();

    // ------- Phase 2a: 4-dir ew (E,SW,S,SE) over rows 0..34, paired dots -------
    if (interior) {
        // Unpredicated: region-edge out-of-window reads land in valid smem / pad.
        // Affected ew slots (E col35, SW col0, SE col35) are never consumed.
        for (int idx = tid; idx < NP2; idx += NTHREADS) {
            const u64 a01 = sA[idx], a23 = sB[idx], a45 = sC[idx], a67 = sD[idx];
            const float a8 = sE[idx];
            #pragma unroll
            for (int t = 0; t < 4; t++) {
                const int o = (t == 0) ? 1 : (t == 1) ? (RF - 1) : (t == 2) ? RF : (RF + 1);
                const int j = idx + o;
                u64 acc = fmul2(a01, sA[j]);
                acc = ffma2(a23, sB[j], acc);
                acc = ffma2(a45, sC[j], acc);
                acc = ffma2(a67, sD[j], acc);
                float lo, hi; upk2(lo, hi, acc);
                float s = fmaf(a8, sE[j], lo + hi);
                sEw[(t + 1) * NP2 + idx] = eclip(s);
            }
        }
    } else {
        for (int idx = tid; idx < NP2; idx += NTHREADS) {
            const int ry = idx / RF;
            const int rx = idx - ry * RF;
            const int gy = y0 - 2 + ry;
            const int gx = x0 - 2 + rx;
            if (((unsigned)gy < (unsigned)Hc) && ((unsigned)gx < (unsigned)Wc)) {
                float a[9], b[9];
                load_vec(sA, sB, sC, sD, sE, idx, a);
                float e1 = 0.f, e2 = 0.f, e3 = 0.f, e4 = 0.f;
                if (rx + 1 < RF && (unsigned)(gx + 1) < (unsigned)Wc) {
                    load_vec(sA, sB, sC, sD, sE, idx + 1, b);
                    e1 = eclip(dot9s(a, b));
                }
                if (rx - 1 >= 0 && (unsigned)(gy + 1) < (unsigned)Hc &&
                    (unsigned)(gx - 1) < (unsigned)Wc) {
                    load_vec(sA, sB, sC, sD, sE, idx + RF - 1, b);
                    e2 = eclip(dot9s(a, b));
                }
                if ((unsigned)(gy + 1) < (unsigned)Hc) {
                    load_vec(sA, sB, sC, sD, sE, idx + RF, b);
                    e3 = eclip(dot9s(a, b));
                }
                if (rx + 1 < RF && (unsigned)(gy + 1) < (unsigned)Hc &&
                    (unsigned)(gx + 1) < (unsigned)Wc) {
                    load_vec(sA, sB, sC, sD, sE, idx + RF + 1, b);
                    e4 = eclip(dot9s(a, b));
                }
                sEw[NP2 + idx] = e1; sEw[2 * NP2 + idx] = e2;
                sEw[3 * NP2 + idx] = e3; sEw[4 * NP2 + idx] = e4;
            } else {
                sEw[NP2 + idx] = 0.f; sEw[2 * NP2 + idx] = 0.f;
                sEw[3 * NP2 + idx] = 0.f; sEw[4 * NP2 + idx] = 0.f;
            }
        }
    }
    __syncthreads();

    // ------- Phase 2b: deg -> dinv gather + prescaled paired sig, over 34x34 -------
    if (interior) {
        const int pbase = (y0 - 1) * Wc + (x0 - 1);
        for (int idx = tid; idx < ND; idx += NTHREADS) {
            const int ly = idx / RD;
            const int lx = idx - ly * RD;
            const int r = (ly + 1) * RF + (lx + 1);
            float deg = sEw[r] + sEw[NP2 + r] + sEw[2 * NP2 + r]
                      + sEw[3 * NP2 + r] + sEw[4 * NP2 + r];
            deg += sEw[4 * NP2 + r - RF - 1];  // NW = SE of up-left
            deg += sEw[3 * NP2 + r - RF];      // N  = S  of up
            deg += sEw[2 * NP2 + r - RF + 1];  // NE = SW of up-right
            deg += sEw[NP2 + r - 1];           // W  = E  of left
            const float dinv = rsqrtf(deg);    // deg >= 1
            const int p = pbase + ly * Wc + lx;
            sP01[idx] = pk2(__ldg(sigbg + p) * dinv, __ldg(sigbg + Nn + p) * dinv);
            sP2[idx]  = __ldg(sigbg + 2 * Nn + p) * dinv;
            sDv[idx]  = dinv;
        }
    } else {
        for (int idx = tid; idx < ND; idx += NTHREADS) {
            const int ly = idx / RD;
            const int lx = idx - ly * RD;
            const int gy = y0 - 1 + ly;
            const int gx = x0 - 1 + lx;
            const bool inb = ((unsigned)gy < (unsigned)Hc) && ((unsigned)gx < (unsigned)Wc);
            const int r = (ly + 1) * RF + (lx + 1);
            float dinv = 0.f;
            if (inb) {
                float deg = sEw[r] + sEw[NP2 + r] + sEw[2 * NP2 + r]
                          + sEw[3 * NP2 + r] + sEw[4 * NP2 + r];
                deg += sEw[4 * NP2 + r - RF - 1];
                deg += sEw[3 * NP2 + r - RF];
                deg += sEw[2 * NP2 + r - RF + 1];
                deg += sEw[NP2 + r - 1];
                dinv = rsqrtf(deg);
            }
            const int p = gy * Wc + gx;
            const float s0 = inb ? __ldg(sigbg + p) * dinv          : 0.f;
            const float s1 = inb ? __ldg(sigbg + Nn + p) * dinv     : 0.f;
            const float s2 = inb ? __ldg(sigbg + 2 * Nn + p) * dinv : 0.f;
            sP01[idx] = pk2(s0, s1);
            sP2[idx]  = s2;
            sDv[idx]  = dinv;
        }
    }
    __syncthreads();

    // ---------------- Phase 3: aggregation + output ----------------
    // out_c = s'_c/dp - dp * S_c,  S_c = sum_t ew_t * s'_{c,nb(t)}
    float* __restrict__ outbg = out + (size_t)bg * Cc * Nn;
    for (int idx = tid; idx < TILE * TILE; idx += NTHREADS) {
        const int ly = idx >> 5;
        const int lx = idx & 31;
        const int r = (ly + 2) * RF + (lx + 2);   // region coords
        const int d = (ly + 1) * RD + (lx + 1);   // RD coords

        const float dp = sDv[d];
        u64 S01 = 0ull;
        float S2 = 0.f;

        #define GLR_ACC(nn, ww) do {                     \
            const float _w = (ww);                       \
            const int _n = (nn);                         \
            S01 = ffma2(sP01[_n], pk2(_w, _w), S01);     \
            S2  = fmaf(sP2[_n], _w, S2);                 \
        } while (0)

        GLR_ACC(d - RD - 1, sEw[4 * NP2 + r - RF - 1]);  // NW
        GLR_ACC(d - RD,     sEw[3 * NP2 + r - RF]);      // N
        GLR_ACC(d - RD + 1, sEw[2 * NP2 + r - RF + 1]);  // NE
        GLR_ACC(d - 1,      sEw[NP2 + r - 1]);           // W
        const u64 c01 = sP01[d];
        const float c2 = sP2[d];
        {
            const float w = sEw[r];                      // self
            S01 = ffma2(c01, pk2(w, w), S01);
            S2  = fmaf(c2, w, S2);
        }
        GLR_ACC(d + 1,      sEw[NP2 + r]);               // E
        GLR_ACC(d + RD - 1, sEw[2 * NP2 + r]);           // SW
        GLR_ACC(d + RD,     sEw[3 * NP2 + r]);           // S
        GLR_ACC(d + RD + 1, sEw[4 * NP2 + r]);           // SE
        #undef GLR_ACC

        float S0, S1; upk2(S0, S1, S01);
        float c0, c1; upk2(c0, c1, c01);
        const float inv = __fdividef(1.0f, dp);          // dp in (0,1]
        const int p = (y0 + ly) * Wc + (x0 + lx);
        outbg[p]          = fmaf(-dp, S0, c0 * inv);
        outbg[Nn + p]     = fmaf(-dp, S1, c1 * inv);
        outbg[2 * Nn + p] = fmaf(-dp, S2, c2 * inv);
    }
}

extern "C" void kernel_launch(void* const* d_in, const int* in_sizes, int n_in,
                              void* d_out, int out_size) {
    const float* img = (const float*)d_in[0];  // (B,G,F,H,W)
    const float* sig = (const float*)d_in[1];  // (B,G,C,H,W)
    const float* M   = (const float*)d_in[2];  // (G,F,F)
    float* out = (float*)d_out;

    cudaFuncSetAttribute(glr_fused_kernel,
                         cudaFuncAttributeMaxDynamicSharedMemorySize, SMEM_BYTES);

    // Fill padded constant multiM with ONE async 2D copy (no repack kernel):
    // src rows = 9 floats (36 B), dst rows = 10 floats (40 B), 36 rows (G*F).
    // Pad lane (5th pair hi) is never written; __constant__ zero-init keeps it 0,
    // and the kernel never consumes it regardless.
    void* cMp_addr = nullptr;
    cudaGetSymbolAddress(&cMp_addr, cMp);
    cudaMemcpy2DAsync(cMp_addr, 40, M, 36, 36, Gc * Fc,
                      cudaMemcpyDeviceToDevice, 0);

    dim3 grid(Wc / TILE, Hc / TILE, Bc * Gc);
    glr_fused_kernel<<<grid, NTHREADS, SMEM_BYTES>>>(img, sig, out);
}